// round 8
// baseline (speedup 1.0000x reference)
#include <cuda_runtime.h>

// x: (B=64, W=512, H=48, M=64) fp32, row-major.
// out[b, ((iw*6 + ih)*64 + m)] = max over w in [iw*32, iw*32+32), h in [ih*8, ih*8+8).
// Exact bins: 512/16 = 32, 48/6 = 8.
//
// Single-wave persistent variant: grid (18, 64) = 1152 CTAs (~0.97 wave at
// 8 CTAs/SM). Each CTA strides over the 96 (iw,ih) tiles of its batch b:
// t = bx, bx+18, ... < 96 (5-6 tiles/CTA). Per tile: same 16-deep unrolled
// LDG.128 body as the R1 best (MLP 16), smem fold, float4 store. Removes the
// 4 wave transitions and the 0.19-wave tail of the 6144-CTA grid.

constexpr int B_  = 64;
constexpr int W_  = 512;
constexpr int H_  = 48;
constexpr int M_  = 64;
constexpr int M4  = M_ / 4;   // 16
constexpr int PW  = 16;
constexpr int PH  = 6;
constexpr int WB  = W_ / PW;  // 32
constexpr int HB  = H_ / PH;  // 8
constexpr int TILES = PW * PH;  // 96 tiles per batch
constexpr int GX  = 18;         // 18*64 = 1152 CTAs ~= one wave

__device__ __forceinline__ float4 max4(float4 a, float4 b) {
    float4 r;
    r.x = fmaxf(a.x, b.x);
    r.y = fmaxf(a.y, b.y);
    r.z = fmaxf(a.z, b.z);
    r.w = fmaxf(a.w, b.w);
    return r;
}

__global__ __launch_bounds__(256, 8)
void dap_pool_kernel(const float4* __restrict__ x4, float4* __restrict__ out4) {
    const int b  = blockIdx.y;   // 0..63

    const int tid = threadIdx.x;       // 0..255
    const int m4  = tid & 15;          // float4 lane over M
    const int sub = tid >> 4;          // 0..15 window subsets

    const float4* __restrict__ xbatch = x4 + (size_t)b * W_ * H_ * M4;
    float4* __restrict__ obatch = out4 + (size_t)b * (TILES * M4);

    __shared__ float4 smem[16][M4];

    for (int t = blockIdx.x; t < TILES; t += GX) {
        const int iw = t / PH;         // 0..15
        const int ih = t - iw * PH;    // 0..5

        const float4* __restrict__ xb =
            xbatch + ((size_t)(iw * WB) * H_ + (size_t)(ih * HB)) * M4 + m4;

        // 32w x 8h window = 256 cells; this thread covers c = sub + 16*i,
        // fully unrolled in one batch (MLP 16), single accumulator.
        float4 acc = make_float4(-INFINITY, -INFINITY, -INFINITY, -INFINITY);
#pragma unroll
        for (int i = 0; i < 16; i++) {
            const int c  = sub + (i << 4);   // 0..255
            const int wl = c >> 3;           // 0..31
            const int hl = c & 7;            // 0..7
            acc = max4(acc, __ldg(xb + ((size_t)wl * H_ + hl) * M4));
        }

        smem[sub][m4] = acc;
        __syncthreads();

        if (tid < M4) {
            float4 r = smem[0][tid];
#pragma unroll
            for (int s = 1; s < 16; s++) r = max4(r, smem[s][tid]);
            obatch[(size_t)t * M4 + tid] = r;
        }
        __syncthreads();   // smem WAR before next tile
    }
}

extern "C" void kernel_launch(void* const* d_in, const int* in_sizes, int n_in,
                              void* d_out, int out_size) {
    const float4* x4 = (const float4*)d_in[0];
    float4* out4 = (float4*)d_out;
    dim3 grid(GX, B_);
    dap_pool_kernel<<<grid, 256>>>(x4, out4);
}

// round 9
// speedup vs baseline: 1.1683x; 1.1683x over previous
#include <cuda_runtime.h>

// x: (B=64, W=512, H=48, M=64) fp32, row-major.
// out[b, ((iw*6 + ih)*64 + m)] = max over w in [iw*32, iw*32+32), h in [ih*8, ih*8+8) of x[b,w,h,m]
// Exact bins: 512/16 = 32, 48/6 = 8 (round(k*p) boundaries are integral).
//
// FINAL (measured best across 8 rounds): one CTA per (b,iw,ih) output tile,
// 6144 CTAs x 256 threads, 32 regs (RF fully allocated at 8 CTAs/SM, occ 96%).
// Each thread: 16 fully unrolled independent LDG.128 (MLP 16), perfectly
// coalesced over M. Compulsory-traffic bound: 402.7 MB read exactly once at
// ~6.7-6.8 TB/s (~85% of 8 TB/s spec) = the achieved HBM ceiling for this
// pattern. Tested and rejected: lower-occupancy locality restructure (-4%),
// __ldcs/grid-order/batch-split (neutral), single-barrier tail (neutral),
// persistent single-wave grid (-17%: per-tile barriers drain MLP; hardware
// CTA replacement is free).

constexpr int B_  = 64;
constexpr int W_  = 512;
constexpr int H_  = 48;
constexpr int M_  = 64;
constexpr int PW  = 16;
constexpr int PH  = 6;
constexpr int WB  = W_ / PW;  // 32
constexpr int HB  = H_ / PH;  // 8

__device__ __forceinline__ float4 max4(float4 a, float4 b) {
    float4 r;
    r.x = fmaxf(a.x, b.x);
    r.y = fmaxf(a.y, b.y);
    r.z = fmaxf(a.z, b.z);
    r.w = fmaxf(a.w, b.w);
    return r;
}

__global__ __launch_bounds__(256, 8)
void dap_pool_kernel(const float* __restrict__ x, float* __restrict__ out) {
    const int iw = blockIdx.x;   // 0..15
    const int ih = blockIdx.y;   // 0..5
    const int b  = blockIdx.z;   // 0..63

    const int tid = threadIdx.x;       // 0..255
    const int m4  = tid & 15;          // float4 lane over M (16 * 4 = 64)
    const int sub = tid >> 4;          // 0..15 window subsets

    // Base pointer for this (b, iw, ih) tile, as float4 over M.
    const float4* __restrict__ xb =
        reinterpret_cast<const float4*>(x) +
        ((size_t)b * W_ * H_ + (size_t)(iw * WB) * H_ + (size_t)(ih * HB)) * (M_ / 4);

    // Window has WB*HB = 256 cells; each thread handles 16 cells: c = sub + 16*i.
    float4 acc = make_float4(-INFINITY, -INFINITY, -INFINITY, -INFINITY);
#pragma unroll
    for (int i = 0; i < 16; i++) {
        const int c = sub + (i << 4);      // 0..255
        const int wl = c >> 3;             // 0..31  (local w)
        const int hl = c & 7;              // 0..7   (local h)
        const float4 v = __ldg(&xb[((size_t)wl * H_ + hl) * (M_ / 4) + m4]);
        acc = max4(acc, v);
    }

    // Tree reduce across the 16 subsets in shared memory.
    __shared__ float4 smem[256];
    smem[tid] = acc;
    __syncthreads();
#pragma unroll
    for (int st = 128; st >= 16; st >>= 1) {
        if (tid < st) smem[tid] = max4(smem[tid], smem[tid + st]);
        __syncthreads();
    }

    if (tid < 16) {
        // out[b, (iw*PH + ih)*M + m4*4 .. +3]
        float4* o4 = reinterpret_cast<float4*>(out);
        o4[(size_t)b * (PW * PH * (M_ / 4)) + (size_t)(iw * PH + ih) * (M_ / 4) + m4] = smem[tid];
    }
}

extern "C" void kernel_launch(void* const* d_in, const int* in_sizes, int n_in,
                              void* d_out, int out_size) {
    const float* x = (const float*)d_in[0];
    float* out = (float*)d_out;
    dim3 grid(PW, PH, B_);
    dap_pool_kernel<<<grid, 256>>>(x, out);
}